// round 13
// baseline (speedup 1.0000x reference)
#include <cuda_runtime.h>
#include <cuda_bf16.h>
#include <cstdint>

#define NB   16
#define WIN  128
#define KF   256
#define EMB  256

typedef unsigned long long u64;

#define ADD2(d, a, b) asm("add.rn.f32x2 %0, %1, %2;" : "=l"(d) : "l"(a), "l"(b))
#define FMA2(d, a, b, c) asm("fma.rn.f32x2 %0, %1, %2, %3;" : "=l"(d) : "l"(a), "l"(b), "l"(c))
#define UNPK(lo, hi, v) asm("mov.b64 {%0, %1}, %2;" : "=f"(lo), "=f"(hi) : "l"(v))
#define PK(d, lo, hi) asm("mov.b64 %0, {%1, %2};" : "=l"(d) : "f"(lo), "f"(hi))
#define ABSMASK 0x7FFFFFFF7FFFFFFFull

#define MMA16816(d, a, b0v, b1v) \
    asm volatile("mma.sync.aligned.m16n8k16.row.col.f32.bf16.bf16.f32 " \
        "{%0,%1,%2,%3}, {%4,%5,%6,%7}, {%8,%9}, {%0,%1,%2,%3};" \
        : "+f"((d)[0]), "+f"((d)[1]), "+f"((d)[2]), "+f"((d)[3]) \
        : "r"((a)[0]), "r"((a)[1]), "r"((a)[2]), "r"((a)[3]), "r"(b0v), "r"(b1v))

// ---------------- device scratch --------------------------------------------
__device__ float g_UI[NB * KF * EMB];
__device__ float g_HJ[NB * KF * EMB];
__device__ float g_ATT[NB * KF * KF];
__device__ float g_MS[NB * KF * 4 * 2];
// pre-converted bf16 operands
__device__ __nv_bfloat16 g_Xhi[NB * KF * WIN];   // x^T: [b][k][w]
__device__ __nv_bfloat16 g_Xlo[NB * KF * WIN];
__device__ __nv_bfloat16 g_Whi[512 * WIN];       // [e'][w]; e'<256: W1, else W2
__device__ __nv_bfloat16 g_Wlo[512 * WIN];

// ============================================================================
// convX: transpose x -> [b][k][w] bf16 hi/lo; spare capacity converts W.
// grid (8 ktiles, 4 wtiles, NB), block 256 (32x8).
// ============================================================================
__global__ __launch_bounds__(256)
void convX(const float* __restrict__ x, const float* __restrict__ lw)
{
    __shared__ float tile[32][33];
    const int b  = blockIdx.z;
    const int k0 = blockIdx.x * 32;
    const int w0 = blockIdx.y * 32;
    const int tx = threadIdx.x & 31;
    const int ty = threadIdx.x >> 5;

    #pragma unroll
    for (int i = 0; i < 4; ++i)
        tile[ty + i * 8][tx] = x[((size_t)b * WIN + w0 + ty + i * 8) * KF + k0 + tx];
    __syncthreads();
    #pragma unroll
    for (int i = 0; i < 4; ++i) {
        int k = k0 + ty + i * 8;
        float v = tile[tx][ty + i * 8];
        __nv_bfloat16 h = __float2bfloat16_rn(v);
        __nv_bfloat16 l = __float2bfloat16_rn(v - __bfloat162float(h));
        size_t o = ((size_t)b * KF + k) * WIN + w0 + tx;
        g_Xhi[o] = h;
        g_Xlo[o] = l;
    }

    // W conversion on the 8 (z==0, y==0) blocks: 64K elements / 2048 threads
    if (b == 0 && blockIdx.y == 0) {
        int base = (blockIdx.x * 256 + threadIdx.x) * 32;
        for (int q = 0; q < 32; ++q) {
            int idx = base + q;                   // [0, 65536)
            int ep = idx >> 7, w = idx & 127;
            float v = lw[(size_t)(ep & 255) * (2 * WIN) + ((ep >> 8) ? WIN : 0) + w];
            __nv_bfloat16 h = __float2bfloat16_rn(v);
            __nv_bfloat16 l = __float2bfloat16_rn(v - __bfloat162float(h));
            g_Whi[idx] = h;
            g_Wlo[idx] = l;
        }
    }
}

// ============================================================================
// gemmA_mma: UI/HJ via mma.sync bf16 3-term split, operands pre-converted.
// CTA: 128 rows x 64 e', K=128. smem 87KB -> 2 CTAs/SM. Grid 256.
// Phase 1: hh (Ahi*Bhi) + hl (Ahi*Blo[buf]); Phase 2: lh (Alo[buf]*Bhi).
// ============================================================================
#define PITCH 136
#define A_ELEMS (128 * PITCH)
#define B_ELEMS (64 * PITCH)
#define SM_GA_TOTAL ((A_ELEMS + B_ELEMS + A_ELEMS) * 2)   // 88.6 KB

__global__ __launch_bounds__(256)
void gemmA_mma(const float* __restrict__ lb)
{
    extern __shared__ __nv_bfloat16 sg[];
    __nv_bfloat16* sAhi = sg;                      // [128][PITCH]
    __nv_bfloat16* sBhi = sAhi + A_ELEMS;          // [64][PITCH]
    __nv_bfloat16* sBuf = sBhi + B_ELEMS;          // [128][PITCH] (Blo then Alo)

    const int t = threadIdx.x;
    const int rtile = blockIdx.y;                  // 0..31
    const int b  = rtile >> 1;
    const int k0 = (rtile & 1) * 128;
    const int ep = blockIdx.x * 64;                // 0..448
    const int side = (ep >= 256);
    const int eb   = ep & 255;

    // ---- fill: pure bf16 16B-coalesced loads ------------------------------
    const uint4* gx = (const uint4*)(g_Xhi + ((size_t)b * KF + k0) * WIN);
    for (int idx = t; idx < 128 * 16; idx += 256) {
        int r = idx >> 4, c = idx & 15;
        *(uint4*)(sAhi + r * PITCH + c * 8) = gx[r * 16 + c];
    }
    const uint4* gw = (const uint4*)(g_Whi + (size_t)ep * WIN);
    for (int idx = t; idx < 64 * 16; idx += 256) {
        int r = idx >> 4, c = idx & 15;
        *(uint4*)(sBhi + r * PITCH + c * 8) = gw[r * 16 + c];
    }
    const uint4* gwl = (const uint4*)(g_Wlo + (size_t)ep * WIN);
    for (int idx = t; idx < 64 * 16; idx += 256) {
        int r = idx >> 4, c = idx & 15;
        *(uint4*)(sBuf + r * PITCH + c * 8) = gwl[r * 16 + c];
    }
    __syncthreads();

    const int wid = t >> 5, lane = t & 31;
    const int gid = lane >> 2, q = lane & 3;
    const int m0 = (wid & 3) * 32;                 // 2 m-tiles of 16
    const int n0 = (wid >> 2) * 32;                // 4 n-tiles of 8

    float acc[2][4][4];
    #pragma unroll
    for (int mt = 0; mt < 2; ++mt)
        #pragma unroll
        for (int nt = 0; nt < 4; ++nt)
            #pragma unroll
            for (int r = 0; r < 4; ++r) acc[mt][nt][r] = 0.f;

    // phase 1: hh and hl (A = sAhi; B = sBhi then sBuf=Blo)
    #pragma unroll 1
    for (int s = 0; s < 2; ++s) {
        const __nv_bfloat16* pb = s ? sBuf : sBhi;
        #pragma unroll 1
        for (int ks = 0; ks < 8; ++ks) {
            const int kb = ks * 16 + q * 2;
            uint32_t afr[2][4];
            #pragma unroll
            for (int mt = 0; mt < 2; ++mt) {
                const __nv_bfloat16* ab = sAhi + (m0 + mt * 16 + gid) * PITCH + kb;
                afr[mt][0] = *(const uint32_t*)(ab);
                afr[mt][1] = *(const uint32_t*)(ab + 8 * PITCH);
                afr[mt][2] = *(const uint32_t*)(ab + 8);
                afr[mt][3] = *(const uint32_t*)(ab + 8 * PITCH + 8);
            }
            #pragma unroll
            for (int nt = 0; nt < 4; ++nt) {
                const __nv_bfloat16* bb = pb + (n0 + nt * 8 + gid) * PITCH + kb;
                uint32_t b0 = *(const uint32_t*)(bb);
                uint32_t b1 = *(const uint32_t*)(bb + 8);
                MMA16816(acc[0][nt], afr[0], b0, b1);
                MMA16816(acc[1][nt], afr[1], b0, b1);
            }
        }
    }

    // swap buffer to Alo
    __syncthreads();
    const uint4* gxl = (const uint4*)(g_Xlo + ((size_t)b * KF + k0) * WIN);
    for (int idx = t; idx < 128 * 16; idx += 256) {
        int r = idx >> 4, c = idx & 15;
        *(uint4*)(sBuf + r * PITCH + c * 8) = gxl[r * 16 + c];
    }
    __syncthreads();

    // phase 2: lh (A = sBuf=Alo; B = sBhi)
    #pragma unroll 1
    for (int ks = 0; ks < 8; ++ks) {
        const int kb = ks * 16 + q * 2;
        uint32_t afr[2][4];
        #pragma unroll
        for (int mt = 0; mt < 2; ++mt) {
            const __nv_bfloat16* ab = sBuf + (m0 + mt * 16 + gid) * PITCH + kb;
            afr[mt][0] = *(const uint32_t*)(ab);
            afr[mt][1] = *(const uint32_t*)(ab + 8 * PITCH);
            afr[mt][2] = *(const uint32_t*)(ab + 8);
            afr[mt][3] = *(const uint32_t*)(ab + 8 * PITCH + 8);
        }
        #pragma unroll
        for (int nt = 0; nt < 4; ++nt) {
            const __nv_bfloat16* bb = sBhi + (n0 + nt * 8 + gid) * PITCH + kb;
            uint32_t b0 = *(const uint32_t*)(bb);
            uint32_t b1 = *(const uint32_t*)(bb + 8);
            MMA16816(acc[0][nt], afr[0], b0, b1);
            MMA16816(acc[1][nt], afr[1], b0, b1);
        }
    }

    // ---- epilogue: stage (reuse smem), coalesced store ---------------------
    float* sStage = (float*)sg;                    // [128][68] = 34.8KB
    __syncthreads();
    #pragma unroll
    for (int mt = 0; mt < 2; ++mt)
        #pragma unroll
        for (int nt = 0; nt < 4; ++nt) {
            int row = m0 + mt * 16 + gid;
            int col = n0 + nt * 8 + q * 2;
            sStage[row * 68 + col]           = acc[mt][nt][0];
            sStage[row * 68 + col + 1]       = acc[mt][nt][1];
            sStage[(row + 8) * 68 + col]     = acc[mt][nt][2];
            sStage[(row + 8) * 68 + col + 1] = acc[mt][nt][3];
        }
    __syncthreads();
    float* dst = (side ? g_HJ : g_UI) + ((size_t)b * KF + k0) * EMB + eb;
    for (int idx = t; idx < 128 * 64; idx += 256) {
        int r = idx >> 6, c = idx & 63;
        float v = sStage[r * 68 + c];
        if (!side) v += __ldg(lb + eb + c);
        dst[(size_t)r * EMB + c] = v;
    }
}

// ============================================================================
// kernB: e = 0.6(dot_i+dot_j) + sum 0.4a|u+v| + bias; store exp(e - m_tile);
// partials -> g_MS.
// ============================================================================
#define BP 260
__global__ __launch_bounds__(256, 2)
void kernB(const float* __restrict__ a, const float* __restrict__ ab)
{
    extern __shared__ float sm[];
    float* sUI = sm;
    float* sHJ = sUI + 32 * BP;
    float* sA4 = sHJ + 64 * BP;
    float* sAI = sA4 + 256;
    float* sAJ = sAI + 32;

    const int b  = blockIdx.z;
    const int i0 = blockIdx.y * 32;
    const int jt = blockIdx.x;
    const int j0 = jt * 64;
    const int t  = threadIdx.x;

    const float4* gu = (const float4*)(g_UI + ((size_t)b * KF + i0) * EMB);
    for (int idx = t; idx < 32 * 64; idx += 256) {
        int r = idx >> 6, c = idx & 63;
        *(float4*)(sUI + r * BP + c * 4) = gu[r * 64 + c];
    }
    const float4* gh = (const float4*)(g_HJ + ((size_t)b * KF + j0) * EMB);
    for (int idx = t; idx < 64 * 64; idx += 256) {
        int r = idx >> 6, c = idx & 63;
        *(float4*)(sHJ + r * BP + c * 4) = gh[r * 64 + c];
    }
    sA4[t] = 0.4f * a[t];
    __syncthreads();

    {
        const int warp = t >> 5, lane = t & 31;
        #pragma unroll
        for (int rr = 0; rr < 4; ++rr) {
            int r = warp * 4 + rr;
            float s = 0.f;
            #pragma unroll
            for (int q = 0; q < 8; ++q) s += sUI[r * BP + lane + q * 32] * sA4[lane + q * 32];
            #pragma unroll
            for (int off = 16; off; off >>= 1) s += __shfl_xor_sync(0xffffffffu, s, off);
            if (lane == 0) sAI[r] = 1.5f * s;
        }
        #pragma unroll
        for (int rr = 0; rr < 8; ++rr) {
            int r = warp * 8 + rr;
            float s = 0.f;
            #pragma unroll
            for (int q = 0; q < 8; ++q) s += sHJ[r * BP + lane + q * 32] * sA4[lane + q * 32];
            #pragma unroll
            for (int off = 16; off; off >>= 1) s += __shfl_xor_sync(0xffffffffu, s, off);
            if (lane == 0) sAJ[r] = 1.5f * s;
        }
    }
    __syncthreads();

    const int ti = t >> 4;
    const int jl = t & 15;
    const ulonglong2* uq0 = (const ulonglong2*)(sUI + ti * BP);
    const ulonglong2* uq1 = (const ulonglong2*)(sUI + (ti + 16) * BP);
    const ulonglong2* vq[4];
    #pragma unroll
    for (int q = 0; q < 4; ++q) vq[q] = (const ulonglong2*)(sHJ + (jl + q * 16) * BP);
    const ulonglong2* aq = (const ulonglong2*)sA4;

    u64 acc0[4], acc1[4];
    #pragma unroll
    for (int q = 0; q < 4; ++q) { acc0[q] = 0ull; acc1[q] = 0ull; }

    #pragma unroll 2
    for (int s = 0; s < 64; ++s) {
        ulonglong2 ae = aq[s], u0 = uq0[s], u1 = uq1[s];
        #pragma unroll
        for (int q = 0; q < 4; ++q) {
            ulonglong2 v = vq[q][s];
            u64 s0x, s0y, s1x, s1y;
            ADD2(s0x, u0.x, v.x); ADD2(s0y, u0.y, v.y);
            ADD2(s1x, u1.x, v.x); ADD2(s1y, u1.y, v.y);
            s0x &= ABSMASK; s0y &= ABSMASK;
            s1x &= ABSMASK; s1y &= ABSMASK;
            FMA2(acc0[q], s0x, ae.x, acc0[q]);
            FMA2(acc0[q], s0y, ae.y, acc0[q]);
            FMA2(acc1[q], s1x, ae.x, acc1[q]);
            FMA2(acc1[q], s1y, ae.y, acc1[q]);
        }
    }

    const float ai0 = sAI[ti], ai1 = sAI[ti + 16];
    float v0[4], v1[4];
    #pragma unroll
    for (int q = 0; q < 4; ++q) {
        int jc = jl + q * 16;
        int j  = j0 + jc;
        float lo, hi;
        UNPK(lo, hi, acc0[q]);
        v0[q] = lo + hi + ai0 + sAJ[jc] + ab[(size_t)(i0 + ti) * KF + j];
        UNPK(lo, hi, acc1[q]);
        v1[q] = lo + hi + ai1 + sAJ[jc] + ab[(size_t)(i0 + ti + 16) * KF + j];
    }
    float m0 = fmaxf(fmaxf(v0[0], v0[1]), fmaxf(v0[2], v0[3]));
    float m1 = fmaxf(fmaxf(v1[0], v1[1]), fmaxf(v1[2], v1[3]));
    #pragma unroll
    for (int off = 8; off; off >>= 1) {
        m0 = fmaxf(m0, __shfl_xor_sync(0xffffffffu, m0, off));
        m1 = fmaxf(m1, __shfl_xor_sync(0xffffffffu, m1, off));
    }
    float e0[4], e1[4];
    float s0 = 0.f, s1 = 0.f;
    #pragma unroll
    for (int q = 0; q < 4; ++q) {
        e0[q] = __expf(v0[q] - m0); s0 += e0[q];
        e1[q] = __expf(v1[q] - m1); s1 += e1[q];
    }
    #pragma unroll
    for (int off = 8; off; off >>= 1) {
        s0 += __shfl_xor_sync(0xffffffffu, s0, off);
        s1 += __shfl_xor_sync(0xffffffffu, s1, off);
    }
    if (jl == 0) {
        size_t r0i = (size_t)(b * KF + i0 + ti) * 8 + jt * 2;
        size_t r1i = (size_t)(b * KF + i0 + ti + 16) * 8 + jt * 2;
        g_MS[r0i] = m0; g_MS[r0i + 1] = s0;
        g_MS[r1i] = m1; g_MS[r1i + 1] = s1;
    }

    float* sE = sm;
    __syncthreads();
    #pragma unroll
    for (int q = 0; q < 4; ++q) {
        int jc = jl + q * 16;
        sE[ti * 66 + jc]        = e0[q];
        sE[(ti + 16) * 66 + jc] = e1[q];
    }
    __syncthreads();
    for (int idx = t; idx < 32 * 64; idx += 256) {
        int r = idx >> 6, c = idx & 63;
        g_ATT[((size_t)b * KF + i0 + r) * KF + j0 + c] = sE[r * 66 + c];
    }
}

// ============================================================================
// kernC: out = sigmoid( sum_jt corr * (att' @ x) )
// ============================================================================
#define CP 68
__global__ __launch_bounds__(256)
void kernC(const float* __restrict__ x, float* __restrict__ out)
{
    __shared__ float sAtt[64 * CP];
    __shared__ float sX[32 * CP];
    __shared__ float sOut[32 * CP];
    __shared__ float sCorr[64 * 4];

    const int b  = blockIdx.z;
    const int w0 = blockIdx.y * 32;
    const int i0 = blockIdx.x * 64;
    const int t  = threadIdx.x;
    const int il = t & 15;
    const int tw = t >> 4;

    if (t < 64) {
        const float* p = g_MS + (size_t)(b * KF + i0 + t) * 8;
        float m[4], s[4];
        #pragma unroll
        for (int q = 0; q < 4; ++q) { m[q] = p[q * 2]; s[q] = p[q * 2 + 1]; }
        float M = fmaxf(fmaxf(m[0], m[1]), fmaxf(m[2], m[3]));
        float ex[4];
        float S = 0.f;
        #pragma unroll
        for (int q = 0; q < 4; ++q) { ex[q] = __expf(m[q] - M); S += s[q] * ex[q]; }
        float inv = 1.0f / S;
        #pragma unroll
        for (int q = 0; q < 4; ++q) sCorr[t * 4 + q] = ex[q] * inv;
    }

    u64 acc[4][2];
    #pragma unroll
    for (int qi = 0; qi < 4; ++qi) { acc[qi][0] = 0ull; acc[qi][1] = 0ull; }

    for (int jt = 0; jt < 4; ++jt) {
        __syncthreads();
        const int j0 = jt * 64;
        for (int idx = t; idx < 64 * 16; idx += 256) {
            int r = idx >> 4, c = idx & 15;
            *(float4*)(sAtt + r * CP + c * 4) =
                *(const float4*)(g_ATT + ((size_t)b * KF + i0 + r) * KF + j0 + c * 4);
        }
        for (int idx = t; idx < 32 * 16; idx += 256) {
            int r = idx >> 4, c = idx & 15;
            *(float4*)(sX + r * CP + c * 4) =
                *(const float4*)(x + ((size_t)b * WIN + w0 + r) * KF + j0 + c * 4);
        }
        __syncthreads();

        const ulonglong2* xq0 = (const ulonglong2*)(sX + tw * CP);
        const ulonglong2* xq1 = (const ulonglong2*)(sX + (tw + 16) * CP);
        const ulonglong2* aq[4];
        #pragma unroll
        for (int qi = 0; qi < 4; ++qi) aq[qi] = (const ulonglong2*)(sAtt + (il + qi * 16) * CP);

        u64 accP[4][2];
        #pragma unroll
        for (int qi = 0; qi < 4; ++qi) { accP[qi][0] = 0ull; accP[qi][1] = 0ull; }

        #pragma unroll 4
        for (int s = 0; s < 16; ++s) {
            ulonglong2 x0 = xq0[s], x1 = xq1[s];
            #pragma unroll
            for (int qi = 0; qi < 4; ++qi) {
                ulonglong2 av = aq[qi][s];
                FMA2(accP[qi][0], av.x, x0.x, accP[qi][0]);
                FMA2(accP[qi][0], av.y, x0.y, accP[qi][0]);
                FMA2(accP[qi][1], av.x, x1.x, accP[qi][1]);
                FMA2(accP[qi][1], av.y, x1.y, accP[qi][1]);
            }
        }
        #pragma unroll
        for (int qi = 0; qi < 4; ++qi) {
            float c = sCorr[(il + qi * 16) * 4 + jt];
            u64 c2; PK(c2, c, c);
            FMA2(acc[qi][0], accP[qi][0], c2, acc[qi][0]);
            FMA2(acc[qi][1], accP[qi][1], c2, acc[qi][1]);
        }
    }

    __syncthreads();
    #pragma unroll
    for (int qi = 0; qi < 4; ++qi) {
        #pragma unroll
        for (int qw = 0; qw < 2; ++qw) {
            float lo, hi; UNPK(lo, hi, acc[qi][qw]);
            float s = lo + hi;
            sOut[(tw + qw * 16) * CP + il + qi * 16] = 1.0f / (1.0f + __expf(-s));
        }
    }
    __syncthreads();
    for (int idx = t; idx < 32 * 64; idx += 256) {
        int r = idx >> 6, c = idx & 63;
        out[((size_t)b * WIN + w0 + r) * KF + i0 + c] = sOut[r * CP + c];
    }
}

// ============================================================================
extern "C" void kernel_launch(void* const* d_in, const int* in_sizes, int n_in,
                              void* d_out, int out_size)
{
    const float* x   = (const float*)d_in[0];
    const float* lw  = (const float*)d_in[1];
    const float* lb  = (const float*)d_in[2];
    const float* a   = (const float*)d_in[3];
    const float* ab  = (const float*)d_in[4];
    float* out = (float*)d_out;

    const int smemB = (32 * BP + 64 * BP + 256 + 32 + 64) * 4;

    cudaFuncSetAttribute(gemmA_mma, cudaFuncAttributeMaxDynamicSharedMemorySize, SM_GA_TOTAL);
    cudaFuncSetAttribute(kernB, cudaFuncAttributeMaxDynamicSharedMemorySize, smemB);

    convX<<<dim3(8, 4, NB), 256>>>(x, lw);
    gemmA_mma<<<dim3(8, 32), 256, SM_GA_TOTAL>>>(lb);
    kernB<<<dim3(4, 8, NB), 256, smemB>>>(a, ab);
    kernC<<<dim3(4, 4, NB), 256>>>(x, out);
}

// round 14
// speedup vs baseline: 1.1492x; 1.1492x over previous
#include <cuda_runtime.h>
#include <cuda_bf16.h>
#include <cstdint>

#define NB   16
#define WIN  128
#define KF   256
#define EMB  256

typedef unsigned long long u64;

#define ADD2(d, a, b) asm("add.rn.f32x2 %0, %1, %2;" : "=l"(d) : "l"(a), "l"(b))
#define FMA2(d, a, b, c) asm("fma.rn.f32x2 %0, %1, %2, %3;" : "=l"(d) : "l"(a), "l"(b), "l"(c))
#define UNPK(lo, hi, v) asm("mov.b64 {%0, %1}, %2;" : "=f"(lo), "=f"(hi) : "l"(v))
#define ABSMASK 0x7FFFFFFF7FFFFFFFull

#define MMA16816(d, a, b0v, b1v) \
    asm volatile("mma.sync.aligned.m16n8k16.row.col.f32.bf16.bf16.f32 " \
        "{%0,%1,%2,%3}, {%4,%5,%6,%7}, {%8,%9}, {%0,%1,%2,%3};" \
        : "+f"((d)[0]), "+f"((d)[1]), "+f"((d)[2]), "+f"((d)[3]) \
        : "r"((a)[0]), "r"((a)[1]), "r"((a)[2]), "r"((a)[3]), "r"(b0v), "r"(b1v))

// ---------------- device scratch --------------------------------------------
__device__ float g_UI[NB * KF * EMB];
__device__ float g_HJ[NB * KF * EMB];
__device__ float g_ATT[NB * KF * KF];        // exp(e - m_tile), per 32-j tile
__device__ float g_MS[NB * KF * 16];         // per (row, 8 j-tiles): max, sumexp

// ============================================================================
// gemmA_mma (R11, measured 29.2us): UI/HJ via mma.sync bf16 3-term split.
// CTA: 128 rows x 128 e', K=128. 8 warps (4m x 2n). Grid 128.
// ============================================================================
#define PITCH 136
#define ASZ   (128 * PITCH)
#define SM_GA_TOTAL (4 * ASZ * 2)         // 139264 B

__global__ __launch_bounds__(256)
void gemmA_mma(const float* __restrict__ x, const float* __restrict__ lw,
               const float* __restrict__ lb)
{
    extern __shared__ __nv_bfloat16 sg[];
    __nv_bfloat16* sAhi = sg;
    __nv_bfloat16* sAlo = sAhi + ASZ;
    __nv_bfloat16* sBhi = sAlo + ASZ;
    __nv_bfloat16* sBlo = sBhi + ASZ;

    const int t = threadIdx.x;
    const int rtile = blockIdx.y;
    const int b  = rtile >> 1;
    const int k0 = (rtile & 1) * 128;
    const int ep = blockIdx.x * 128;
    const int side = (ep >= 256);
    const int eb   = ep & 255;
    const int woff = side ? WIN : 0;

    const float* xb = x + (size_t)b * WIN * KF + k0;
    for (int idx = t; idx < 128 * 128; idx += 256) {
        int m = idx & 127, k = idx >> 7;
        float v = xb[k * KF + m];
        __nv_bfloat16 h = __float2bfloat16_rn(v);
        __nv_bfloat16 l = __float2bfloat16_rn(v - __bfloat162float(h));
        sAhi[m * PITCH + k] = h;
        sAlo[m * PITCH + k] = l;
    }
    for (int idx = t; idx < 128 * 128; idx += 256) {
        int k = idx & 127, n = idx >> 7;
        float v = lw[(eb + n) * (2 * WIN) + woff + k];
        __nv_bfloat16 h = __float2bfloat16_rn(v);
        __nv_bfloat16 l = __float2bfloat16_rn(v - __bfloat162float(h));
        sBhi[n * PITCH + k] = h;
        sBlo[n * PITCH + k] = l;
    }
    __syncthreads();

    const int wid = t >> 5, lane = t & 31;
    const int gid = lane >> 2, q = lane & 3;
    const int m0 = (wid & 3) * 32;
    const int n0 = (wid >> 2) * 64;

    float acc[2][8][4];
    #pragma unroll
    for (int mt = 0; mt < 2; ++mt)
        #pragma unroll
        for (int nt = 0; nt < 8; ++nt)
            #pragma unroll
            for (int r = 0; r < 4; ++r) acc[mt][nt][r] = 0.f;

    #pragma unroll 1
    for (int s = 0; s < 3; ++s) {
        const __nv_bfloat16* pa = (s == 2) ? sAlo : sAhi;
        const __nv_bfloat16* pb = (s == 1) ? sBlo : sBhi;
        #pragma unroll 1
        for (int ks = 0; ks < 8; ++ks) {
            const int kb = ks * 16 + q * 2;
            uint32_t afr[2][4];
            #pragma unroll
            for (int mt = 0; mt < 2; ++mt) {
                const __nv_bfloat16* ab = pa + (m0 + mt * 16 + gid) * PITCH + kb;
                afr[mt][0] = *(const uint32_t*)(ab);
                afr[mt][1] = *(const uint32_t*)(ab + 8 * PITCH);
                afr[mt][2] = *(const uint32_t*)(ab + 8);
                afr[mt][3] = *(const uint32_t*)(ab + 8 * PITCH + 8);
            }
            #pragma unroll
            for (int nt = 0; nt < 8; ++nt) {
                const __nv_bfloat16* bb = pb + (n0 + nt * 8 + gid) * PITCH + kb;
                uint32_t b0 = *(const uint32_t*)(bb);
                uint32_t b1 = *(const uint32_t*)(bb + 8);
                MMA16816(acc[0][nt], afr[0], b0, b1);
                MMA16816(acc[1][nt], afr[1], b0, b1);
            }
        }
    }

    float* sStage = (float*)sg;
    __syncthreads();
    #pragma unroll
    for (int mt = 0; mt < 2; ++mt) {
        #pragma unroll
        for (int nt = 0; nt < 8; ++nt) {
            int row = m0 + mt * 16 + gid;
            int col = n0 + nt * 8 + q * 2;
            sStage[row * 132 + col]           = acc[mt][nt][0];
            sStage[row * 132 + col + 1]       = acc[mt][nt][1];
            sStage[(row + 8) * 132 + col]     = acc[mt][nt][2];
            sStage[(row + 8) * 132 + col + 1] = acc[mt][nt][3];
        }
    }
    __syncthreads();
    float* dst = (side ? g_HJ : g_UI) + ((size_t)b * KF + k0) * EMB + eb;
    for (int idx = t; idx < 128 * 128; idx += 256) {
        int r = idx >> 7, c = idx & 127;
        float v = sStage[r * 132 + c];
        if (!side) v += __ldg(lb + eb + c);
        dst[(size_t)r * EMB + c] = v;
    }
}

// ============================================================================
// kernB: 32 i x 32 j tiles, 1024 blocks, 3 CTAs/SM (24 warps).
// e = 0.6(dot_i+dot_j) + sum 0.4a|u+v| + bias; store exp(e - m_tile);
// (m, sumexp) per 32-j tile -> g_MS[row][jt].
// ============================================================================
#define BP 260
#define SMB ((32 * BP + 32 * BP + 256 + 32 + 32) * 4)
__global__ __launch_bounds__(256, 3)
void kernB(const float* __restrict__ a, const float* __restrict__ ab)
{
    extern __shared__ float sm[];
    float* sUI = sm;                   // [32][260]
    float* sHJ = sUI + 32 * BP;        // [32][260]
    float* sA4 = sHJ + 32 * BP;        // [256]  0.4*a
    float* sAI = sA4 + 256;            // [32]
    float* sAJ = sAI + 32;             // [32]

    const int b  = blockIdx.z;
    const int i0 = blockIdx.y * 32;
    const int jt = blockIdx.x;         // 0..7
    const int j0 = jt * 32;
    const int t  = threadIdx.x;

    const float4* gu = (const float4*)(g_UI + ((size_t)b * KF + i0) * EMB);
    for (int idx = t; idx < 32 * 64; idx += 256) {
        int r = idx >> 6, c = idx & 63;
        *(float4*)(sUI + r * BP + c * 4) = gu[r * 64 + c];
    }
    const float4* gh = (const float4*)(g_HJ + ((size_t)b * KF + j0) * EMB);
    for (int idx = t; idx < 32 * 64; idx += 256) {
        int r = idx >> 6, c = idx & 63;
        *(float4*)(sHJ + r * BP + c * 4) = gh[r * 64 + c];
    }
    sA4[t] = 0.4f * a[t];
    __syncthreads();

    // row dots: 0.6*dot(row, a) = 1.5*dot(row, 0.4a); warp w: 4 UI + 4 HJ rows
    {
        const int warp = t >> 5, lane = t & 31;
        #pragma unroll
        for (int rr = 0; rr < 4; ++rr) {
            int r = warp * 4 + rr;
            float su = 0.f, sh = 0.f;
            #pragma unroll
            for (int q = 0; q < 8; ++q) {
                float av = sA4[lane + q * 32];
                su += sUI[r * BP + lane + q * 32] * av;
                sh += sHJ[r * BP + lane + q * 32] * av;
            }
            #pragma unroll
            for (int off = 16; off; off >>= 1) {
                su += __shfl_xor_sync(0xffffffffu, su, off);
                sh += __shfl_xor_sync(0xffffffffu, sh, off);
            }
            if (lane == 0) { sAI[r] = 1.5f * su; sAJ[r] = 1.5f * sh; }
        }
    }
    __syncthreads();

    const int ti = t >> 4;             // rows ti, ti+16
    const int jl = t & 15;             // cols jl, jl+16
    const ulonglong2* uq0 = (const ulonglong2*)(sUI + ti * BP);
    const ulonglong2* uq1 = (const ulonglong2*)(sUI + (ti + 16) * BP);
    const ulonglong2* vq0 = (const ulonglong2*)(sHJ + jl * BP);
    const ulonglong2* vq1 = (const ulonglong2*)(sHJ + (jl + 16) * BP);
    const ulonglong2* aq = (const ulonglong2*)sA4;

    u64 a00 = 0ull, a01 = 0ull, a10 = 0ull, a11 = 0ull;

    #pragma unroll 4
    for (int s = 0; s < 64; ++s) {
        ulonglong2 ae = aq[s], u0 = uq0[s], u1 = uq1[s];
        ulonglong2 v0 = vq0[s], v1 = vq1[s];
        u64 w;
        ADD2(w, u0.x, v0.x); w &= ABSMASK; FMA2(a00, w, ae.x, a00);
        ADD2(w, u0.y, v0.y); w &= ABSMASK; FMA2(a00, w, ae.y, a00);
        ADD2(w, u0.x, v1.x); w &= ABSMASK; FMA2(a01, w, ae.x, a01);
        ADD2(w, u0.y, v1.y); w &= ABSMASK; FMA2(a01, w, ae.y, a01);
        ADD2(w, u1.x, v0.x); w &= ABSMASK; FMA2(a10, w, ae.x, a10);
        ADD2(w, u1.y, v0.y); w &= ABSMASK; FMA2(a10, w, ae.y, a10);
        ADD2(w, u1.x, v1.x); w &= ABSMASK; FMA2(a11, w, ae.x, a11);
        ADD2(w, u1.y, v1.y); w &= ABSMASK; FMA2(a11, w, ae.y, a11);
    }

    // epilogue
    const float ai0 = sAI[ti], ai1 = sAI[ti + 16];
    const float aj0 = sAJ[jl], aj1 = sAJ[jl + 16];
    float lo, hi;
    float v00, v01, v10, v11;
    UNPK(lo, hi, a00); v00 = lo + hi + ai0 + aj0 + ab[(size_t)(i0 + ti) * KF + j0 + jl];
    UNPK(lo, hi, a01); v01 = lo + hi + ai0 + aj1 + ab[(size_t)(i0 + ti) * KF + j0 + jl + 16];
    UNPK(lo, hi, a10); v10 = lo + hi + ai1 + aj0 + ab[(size_t)(i0 + ti + 16) * KF + j0 + jl];
    UNPK(lo, hi, a11); v11 = lo + hi + ai1 + aj1 + ab[(size_t)(i0 + ti + 16) * KF + j0 + jl + 16];

    float m0 = fmaxf(v00, v01), m1 = fmaxf(v10, v11);
    #pragma unroll
    for (int off = 8; off; off >>= 1) {
        m0 = fmaxf(m0, __shfl_xor_sync(0xffffffffu, m0, off));
        m1 = fmaxf(m1, __shfl_xor_sync(0xffffffffu, m1, off));
    }
    float e00 = __expf(v00 - m0), e01 = __expf(v01 - m0);
    float e10 = __expf(v10 - m1), e11 = __expf(v11 - m1);
    float s0 = e00 + e01, s1 = e10 + e11;
    #pragma unroll
    for (int off = 8; off; off >>= 1) {
        s0 += __shfl_xor_sync(0xffffffffu, s0, off);
        s1 += __shfl_xor_sync(0xffffffffu, s1, off);
    }
    if (jl == 0) {
        size_t r0 = (size_t)(b * KF + i0 + ti) * 16 + jt * 2;
        size_t r1 = (size_t)(b * KF + i0 + ti + 16) * 16 + jt * 2;
        g_MS[r0] = m0; g_MS[r0 + 1] = s0;
        g_MS[r1] = m1; g_MS[r1 + 1] = s1;
    }

    float* sE = sm;                    // [32][36], reuse sUI region
    __syncthreads();
    sE[ti * 36 + jl]             = e00;
    sE[ti * 36 + jl + 16]        = e01;
    sE[(ti + 16) * 36 + jl]      = e10;
    sE[(ti + 16) * 36 + jl + 16] = e11;
    __syncthreads();
    for (int idx = t; idx < 32 * 32; idx += 256) {
        int r = idx >> 5, c = idx & 31;
        g_ATT[((size_t)b * KF + i0 + r) * KF + j0 + c] = sE[r * 36 + c];
    }
}

// ============================================================================
// kernC: 32 i x 32 w tiles, 512 blocks; corr folded into ATT staging.
// out[b,w,i] = sigmoid( sum_j att'[i,j]*corr[i,j/32] * x[w,j] )
// ============================================================================
#define CP 68
__global__ __launch_bounds__(256)
void kernC(const float* __restrict__ x, float* __restrict__ out)
{
    __shared__ float sAtt[32 * CP];
    __shared__ float sX[32 * CP];
    __shared__ float sOut[32 * 36];
    __shared__ float sCorr[32 * 8];

    const int b  = blockIdx.z;
    const int w0 = blockIdx.y * 32;
    const int i0 = blockIdx.x * 32;
    const int t  = threadIdx.x;
    const int il = t & 15;             // i rows: il, il+16
    const int tw = t >> 4;             // w rows: tw, tw+16

    if (t < 32) {
        const float* p = g_MS + (size_t)(b * KF + i0 + t) * 16;
        float m[8], s[8];
        #pragma unroll
        for (int q = 0; q < 8; ++q) { m[q] = p[q * 2]; s[q] = p[q * 2 + 1]; }
        float M = m[0];
        #pragma unroll
        for (int q = 1; q < 8; ++q) M = fmaxf(M, m[q]);
        float ex[8], S = 0.f;
        #pragma unroll
        for (int q = 0; q < 8; ++q) { ex[q] = __expf(m[q] - M); S += s[q] * ex[q]; }
        float inv = 1.0f / S;
        #pragma unroll
        for (int q = 0; q < 8; ++q) sCorr[t * 8 + q] = ex[q] * inv;
    }

    u64 acc00 = 0ull, acc01 = 0ull, acc10 = 0ull, acc11 = 0ull;

    for (int jt = 0; jt < 4; ++jt) {
        __syncthreads();
        const int j0 = jt * 64;
        for (int idx = t; idx < 32 * 16; idx += 256) {
            int r = idx >> 4, c = idx & 15;
            float4 v = *(const float4*)(g_ATT + ((size_t)b * KF + i0 + r) * KF + j0 + c * 4);
            float cr = sCorr[r * 8 + jt * 2 + (c >> 3)];
            v.x *= cr; v.y *= cr; v.z *= cr; v.w *= cr;
            *(float4*)(sAtt + r * CP + c * 4) = v;
        }
        for (int idx = t; idx < 32 * 16; idx += 256) {
            int r = idx >> 4, c = idx & 15;
            *(float4*)(sX + r * CP + c * 4) =
                *(const float4*)(x + ((size_t)b * WIN + w0 + r) * KF + j0 + c * 4);
        }
        __syncthreads();

        const ulonglong2* aq0 = (const ulonglong2*)(sAtt + il * CP);
        const ulonglong2* aq1 = (const ulonglong2*)(sAtt + (il + 16) * CP);
        const ulonglong2* xq0 = (const ulonglong2*)(sX + tw * CP);
        const ulonglong2* xq1 = (const ulonglong2*)(sX + (tw + 16) * CP);

        #pragma unroll 8
        for (int s = 0; s < 16; ++s) {
            ulonglong2 x0 = xq0[s], x1 = xq1[s];
            ulonglong2 a0 = aq0[s], a1 = aq1[s];
            FMA2(acc00, a0.x, x0.x, acc00);
            FMA2(acc00, a0.y, x0.y, acc00);
            FMA2(acc01, a0.x, x1.x, acc01);
            FMA2(acc01, a0.y, x1.y, acc01);
            FMA2(acc10, a1.x, x0.x, acc10);
            FMA2(acc10, a1.y, x0.y, acc10);
            FMA2(acc11, a1.x, x1.x, acc11);
            FMA2(acc11, a1.y, x1.y, acc11);
        }
    }

    __syncthreads();
    float lo, hi;
    UNPK(lo, hi, acc00); sOut[tw * 36 + il]             = 1.0f / (1.0f + __expf(-(lo + hi)));
    UNPK(lo, hi, acc01); sOut[(tw + 16) * 36 + il]      = 1.0f / (1.0f + __expf(-(lo + hi)));
    UNPK(lo, hi, acc10); sOut[tw * 36 + il + 16]        = 1.0f / (1.0f + __expf(-(lo + hi)));
    UNPK(lo, hi, acc11); sOut[(tw + 16) * 36 + il + 16] = 1.0f / (1.0f + __expf(-(lo + hi)));
    __syncthreads();
    for (int idx = t; idx < 32 * 32; idx += 256) {
        int r = idx >> 5, c = idx & 31;
        out[((size_t)b * WIN + w0 + r) * KF + i0 + c] = sOut[r * 36 + c];
    }
}

// ============================================================================
extern "C" void kernel_launch(void* const* d_in, const int* in_sizes, int n_in,
                              void* d_out, int out_size)
{
    const float* x   = (const float*)d_in[0];
    const float* lw  = (const float*)d_in[1];
    const float* lb  = (const float*)d_in[2];
    const float* a   = (const float*)d_in[3];
    const float* ab  = (const float*)d_in[4];
    float* out = (float*)d_out;

    cudaFuncSetAttribute(gemmA_mma, cudaFuncAttributeMaxDynamicSharedMemorySize, SM_GA_TOTAL);
    cudaFuncSetAttribute(kernB, cudaFuncAttributeMaxDynamicSharedMemorySize, SMB);

    gemmA_mma<<<dim3(4, 32), 256, SM_GA_TOTAL>>>(x, lw, lb);
    kernB<<<dim3(8, 8, NB), 256, SMB>>>(a, ab);
    kernC<<<dim3(8, 4, NB), 256>>>(x, out);
}

// round 15
// speedup vs baseline: 1.2487x; 1.0866x over previous
#include <cuda_runtime.h>
#include <cuda_bf16.h>
#include <cstdint>

#define NB   16
#define WIN  128
#define KF   256
#define EMB  256

typedef unsigned long long u64;

#define ADD2(d, a, b) asm("add.rn.f32x2 %0, %1, %2;" : "=l"(d) : "l"(a), "l"(b))
#define FMA2(d, a, b, c) asm("fma.rn.f32x2 %0, %1, %2, %3;" : "=l"(d) : "l"(a), "l"(b), "l"(c))
#define UNPK(lo, hi, v) asm("mov.b64 {%0, %1}, %2;" : "=f"(lo), "=f"(hi) : "l"(v))
#define ABSMASK 0x7FFFFFFF7FFFFFFFull

#define MMA16816(d, a, b0v, b1v) \
    asm volatile("mma.sync.aligned.m16n8k16.row.col.f32.bf16.bf16.f32 " \
        "{%0,%1,%2,%3}, {%4,%5,%6,%7}, {%8,%9}, {%0,%1,%2,%3};" \
        : "+f"((d)[0]), "+f"((d)[1]), "+f"((d)[2]), "+f"((d)[3]) \
        : "r"((a)[0]), "r"((a)[1]), "r"((a)[2]), "r"((a)[3]), "r"(b0v), "r"(b1v))

// ---------------- device scratch --------------------------------------------
__device__ float g_UI[NB * KF * EMB];
__device__ float g_HJ[NB * KF * EMB];
__device__ float g_ATT[NB * KF * KF];        // exp(e - m_tile), per 32-j tile
__device__ float g_MS[NB * KF * 16];         // per (row, 8 j-tiles): max, sumexp

// ============================================================================
// gemmA_mma: UI/HJ via mma.sync bf16 3-term split. 512 threads (16 warps/SM).
// CTA: 128 rows x 128 e', K=128. 16 warps (4m x 4n), each 32m x 32n.
// ============================================================================
#define PITCH 136
#define ASZ   (128 * PITCH)
#define SM_GA_TOTAL (4 * ASZ * 2)         // 139264 B

__global__ __launch_bounds__(512)
void gemmA_mma(const float* __restrict__ x, const float* __restrict__ lw,
               const float* __restrict__ lb)
{
    extern __shared__ __nv_bfloat16 sg[];
    __nv_bfloat16* sAhi = sg;
    __nv_bfloat16* sAlo = sAhi + ASZ;
    __nv_bfloat16* sBhi = sAlo + ASZ;
    __nv_bfloat16* sBlo = sBhi + ASZ;

    const int t = threadIdx.x;
    const int rtile = blockIdx.y;
    const int b  = rtile >> 1;
    const int k0 = (rtile & 1) * 128;
    const int ep = blockIdx.x * 128;
    const int side = (ep >= 256);
    const int eb   = ep & 255;
    const int woff = side ? WIN : 0;

    const float* xb = x + (size_t)b * WIN * KF + k0;
    for (int idx = t; idx < 128 * 128; idx += 512) {
        int m = idx & 127, k = idx >> 7;
        float v = xb[k * KF + m];
        __nv_bfloat16 h = __float2bfloat16_rn(v);
        __nv_bfloat16 l = __float2bfloat16_rn(v - __bfloat162float(h));
        sAhi[m * PITCH + k] = h;
        sAlo[m * PITCH + k] = l;
    }
    for (int idx = t; idx < 128 * 128; idx += 512) {
        int k = idx & 127, n = idx >> 7;
        float v = lw[(eb + n) * (2 * WIN) + woff + k];
        __nv_bfloat16 h = __float2bfloat16_rn(v);
        __nv_bfloat16 l = __float2bfloat16_rn(v - __bfloat162float(h));
        sBhi[n * PITCH + k] = h;
        sBlo[n * PITCH + k] = l;
    }
    __syncthreads();

    const int wid = t >> 5, lane = t & 31;
    const int gid = lane >> 2, q = lane & 3;
    const int m0 = (wid & 3) * 32;            // 2 m-tiles of 16
    const int n0 = (wid >> 2) * 32;           // 4 n-tiles of 8

    float acc[2][4][4];
    #pragma unroll
    for (int mt = 0; mt < 2; ++mt)
        #pragma unroll
        for (int nt = 0; nt < 4; ++nt)
            #pragma unroll
            for (int r = 0; r < 4; ++r) acc[mt][nt][r] = 0.f;

    #pragma unroll 1
    for (int s = 0; s < 3; ++s) {
        const __nv_bfloat16* pa = (s == 2) ? sAlo : sAhi;
        const __nv_bfloat16* pb = (s == 1) ? sBlo : sBhi;
        #pragma unroll 1
        for (int ks = 0; ks < 8; ++ks) {
            const int kb = ks * 16 + q * 2;
            uint32_t afr[2][4];
            #pragma unroll
            for (int mt = 0; mt < 2; ++mt) {
                const __nv_bfloat16* ab = pa + (m0 + mt * 16 + gid) * PITCH + kb;
                afr[mt][0] = *(const uint32_t*)(ab);
                afr[mt][1] = *(const uint32_t*)(ab + 8 * PITCH);
                afr[mt][2] = *(const uint32_t*)(ab + 8);
                afr[mt][3] = *(const uint32_t*)(ab + 8 * PITCH + 8);
            }
            #pragma unroll
            for (int nt = 0; nt < 4; ++nt) {
                const __nv_bfloat16* bb = pb + (n0 + nt * 8 + gid) * PITCH + kb;
                uint32_t b0 = *(const uint32_t*)(bb);
                uint32_t b1 = *(const uint32_t*)(bb + 8);
                MMA16816(acc[0][nt], afr[0], b0, b1);
                MMA16816(acc[1][nt], afr[1], b0, b1);
            }
        }
    }

    float* sStage = (float*)sg;
    __syncthreads();
    #pragma unroll
    for (int mt = 0; mt < 2; ++mt) {
        #pragma unroll
        for (int nt = 0; nt < 4; ++nt) {
            int row = m0 + mt * 16 + gid;
            int col = n0 + nt * 8 + q * 2;
            sStage[row * 132 + col]           = acc[mt][nt][0];
            sStage[row * 132 + col + 1]       = acc[mt][nt][1];
            sStage[(row + 8) * 132 + col]     = acc[mt][nt][2];
            sStage[(row + 8) * 132 + col + 1] = acc[mt][nt][3];
        }
    }
    __syncthreads();
    float* dst = (side ? g_HJ : g_UI) + ((size_t)b * KF + k0) * EMB + eb;
    for (int idx = t; idx < 128 * 128; idx += 512) {
        int r = idx >> 7, c = idx & 127;
        float v = sStage[r * 132 + c];
        if (!side) v += __ldg(lb + eb + c);
        dst[(size_t)r * EMB + c] = v;
    }
}

// ============================================================================
// kernB: 32 i x 32 j tiles, 1024 blocks, 3 CTAs/SM (24 warps).
// e = 0.6(dot_i+dot_j) + sum 0.4a|u+v| + bias; store exp(e - m_tile);
// (m, sumexp) per 32-j tile -> g_MS[row][jt].
// ============================================================================
#define BP 260
#define SMB ((32 * BP + 32 * BP + 256 + 32 + 32) * 4)
__global__ __launch_bounds__(256, 3)
void kernB(const float* __restrict__ a, const float* __restrict__ ab)
{
    extern __shared__ float sm[];
    float* sUI = sm;                   // [32][260]
    float* sHJ = sUI + 32 * BP;        // [32][260]
    float* sA4 = sHJ + 32 * BP;        // [256]  0.4*a
    float* sAI = sA4 + 256;            // [32]
    float* sAJ = sAI + 32;             // [32]

    const int b  = blockIdx.z;
    const int i0 = blockIdx.y * 32;
    const int jt = blockIdx.x;         // 0..7
    const int j0 = jt * 32;
    const int t  = threadIdx.x;

    const float4* gu = (const float4*)(g_UI + ((size_t)b * KF + i0) * EMB);
    for (int idx = t; idx < 32 * 64; idx += 256) {
        int r = idx >> 6, c = idx & 63;
        *(float4*)(sUI + r * BP + c * 4) = gu[r * 64 + c];
    }
    const float4* gh = (const float4*)(g_HJ + ((size_t)b * KF + j0) * EMB);
    for (int idx = t; idx < 32 * 64; idx += 256) {
        int r = idx >> 6, c = idx & 63;
        *(float4*)(sHJ + r * BP + c * 4) = gh[r * 64 + c];
    }
    sA4[t] = 0.4f * a[t];
    __syncthreads();

    // row dots: 0.6*dot(row, a) = 1.5*dot(row, 0.4a); warp w: 4 UI + 4 HJ rows
    {
        const int warp = t >> 5, lane = t & 31;
        #pragma unroll
        for (int rr = 0; rr < 4; ++rr) {
            int r = warp * 4 + rr;
            float su = 0.f, sh = 0.f;
            #pragma unroll
            for (int q = 0; q < 8; ++q) {
                float av = sA4[lane + q * 32];
                su += sUI[r * BP + lane + q * 32] * av;
                sh += sHJ[r * BP + lane + q * 32] * av;
            }
            #pragma unroll
            for (int off = 16; off; off >>= 1) {
                su += __shfl_xor_sync(0xffffffffu, su, off);
                sh += __shfl_xor_sync(0xffffffffu, sh, off);
            }
            if (lane == 0) { sAI[r] = 1.5f * su; sAJ[r] = 1.5f * sh; }
        }
    }
    __syncthreads();

    const int ti = t >> 4;             // rows ti, ti+16
    const int jl = t & 15;             // cols jl, jl+16
    const ulonglong2* uq0 = (const ulonglong2*)(sUI + ti * BP);
    const ulonglong2* uq1 = (const ulonglong2*)(sUI + (ti + 16) * BP);
    const ulonglong2* vq0 = (const ulonglong2*)(sHJ + jl * BP);
    const ulonglong2* vq1 = (const ulonglong2*)(sHJ + (jl + 16) * BP);
    const ulonglong2* aq = (const ulonglong2*)sA4;

    u64 a00 = 0ull, a01 = 0ull, a10 = 0ull, a11 = 0ull;

    #pragma unroll 4
    for (int s = 0; s < 64; ++s) {
        ulonglong2 ae = aq[s], u0 = uq0[s], u1 = uq1[s];
        ulonglong2 v0 = vq0[s], v1 = vq1[s];
        u64 w;
        ADD2(w, u0.x, v0.x); w &= ABSMASK; FMA2(a00, w, ae.x, a00);
        ADD2(w, u0.y, v0.y); w &= ABSMASK; FMA2(a00, w, ae.y, a00);
        ADD2(w, u0.x, v1.x); w &= ABSMASK; FMA2(a01, w, ae.x, a01);
        ADD2(w, u0.y, v1.y); w &= ABSMASK; FMA2(a01, w, ae.y, a01);
        ADD2(w, u1.x, v0.x); w &= ABSMASK; FMA2(a10, w, ae.x, a10);
        ADD2(w, u1.y, v0.y); w &= ABSMASK; FMA2(a10, w, ae.y, a10);
        ADD2(w, u1.x, v1.x); w &= ABSMASK; FMA2(a11, w, ae.x, a11);
        ADD2(w, u1.y, v1.y); w &= ABSMASK; FMA2(a11, w, ae.y, a11);
    }

    // epilogue
    const float ai0 = sAI[ti], ai1 = sAI[ti + 16];
    const float aj0 = sAJ[jl], aj1 = sAJ[jl + 16];
    float lo, hi;
    float v00, v01, v10, v11;
    UNPK(lo, hi, a00); v00 = lo + hi + ai0 + aj0 + ab[(size_t)(i0 + ti) * KF + j0 + jl];
    UNPK(lo, hi, a01); v01 = lo + hi + ai0 + aj1 + ab[(size_t)(i0 + ti) * KF + j0 + jl + 16];
    UNPK(lo, hi, a10); v10 = lo + hi + ai1 + aj0 + ab[(size_t)(i0 + ti + 16) * KF + j0 + jl];
    UNPK(lo, hi, a11); v11 = lo + hi + ai1 + aj1 + ab[(size_t)(i0 + ti + 16) * KF + j0 + jl + 16];

    float m0 = fmaxf(v00, v01), m1 = fmaxf(v10, v11);
    #pragma unroll
    for (int off = 8; off; off >>= 1) {
        m0 = fmaxf(m0, __shfl_xor_sync(0xffffffffu, m0, off));
        m1 = fmaxf(m1, __shfl_xor_sync(0xffffffffu, m1, off));
    }
    float e00 = __expf(v00 - m0), e01 = __expf(v01 - m0);
    float e10 = __expf(v10 - m1), e11 = __expf(v11 - m1);
    float s0 = e00 + e01, s1 = e10 + e11;
    #pragma unroll
    for (int off = 8; off; off >>= 1) {
        s0 += __shfl_xor_sync(0xffffffffu, s0, off);
        s1 += __shfl_xor_sync(0xffffffffu, s1, off);
    }
    if (jl == 0) {
        size_t r0 = (size_t)(b * KF + i0 + ti) * 16 + jt * 2;
        size_t r1 = (size_t)(b * KF + i0 + ti + 16) * 16 + jt * 2;
        g_MS[r0] = m0; g_MS[r0 + 1] = s0;
        g_MS[r1] = m1; g_MS[r1 + 1] = s1;
    }

    float* sE = sm;                    // [32][36], reuse sUI region
    __syncthreads();
    sE[ti * 36 + jl]             = e00;
    sE[ti * 36 + jl + 16]        = e01;
    sE[(ti + 16) * 36 + jl]      = e10;
    sE[(ti + 16) * 36 + jl + 16] = e11;
    __syncthreads();
    for (int idx = t; idx < 32 * 32; idx += 256) {
        int r = idx >> 5, c = idx & 31;
        g_ATT[((size_t)b * KF + i0 + r) * KF + j0 + c] = sE[r * 36 + c];
    }
}

// ============================================================================
// kernC: 32 i x 32 w tiles, 512 blocks; corr folded into ATT staging.
// out[b,w,i] = sigmoid( sum_j att'[i,j]*corr[i,j/32] * x[w,j] )
// ============================================================================
#define CP 68
__global__ __launch_bounds__(256)
void kernC(const float* __restrict__ x, float* __restrict__ out)
{
    __shared__ float sAtt[32 * CP];
    __shared__ float sX[32 * CP];
    __shared__ float sOut[32 * 36];
    __shared__ float sCorr[32 * 8];

    const int b  = blockIdx.z;
    const int w0 = blockIdx.y * 32;
    const int i0 = blockIdx.x * 32;
    const int t  = threadIdx.x;
    const int il = t & 15;             // i rows: il, il+16
    const int tw = t >> 4;             // w rows: tw, tw+16

    if (t < 32) {
        const float* p = g_MS + (size_t)(b * KF + i0 + t) * 16;
        float m[8], s[8];
        #pragma unroll
        for (int q = 0; q < 8; ++q) { m[q] = p[q * 2]; s[q] = p[q * 2 + 1]; }
        float M = m[0];
        #pragma unroll
        for (int q = 1; q < 8; ++q) M = fmaxf(M, m[q]);
        float ex[8], S = 0.f;
        #pragma unroll
        for (int q = 0; q < 8; ++q) { ex[q] = __expf(m[q] - M); S += s[q] * ex[q]; }
        float inv = 1.0f / S;
        #pragma unroll
        for (int q = 0; q < 8; ++q) sCorr[t * 8 + q] = ex[q] * inv;
    }

    u64 acc00 = 0ull, acc01 = 0ull, acc10 = 0ull, acc11 = 0ull;

    for (int jt = 0; jt < 4; ++jt) {
        __syncthreads();
        const int j0 = jt * 64;
        for (int idx = t; idx < 32 * 16; idx += 256) {
            int r = idx >> 4, c = idx & 15;
            float4 v = *(const float4*)(g_ATT + ((size_t)b * KF + i0 + r) * KF + j0 + c * 4);
            float cr = sCorr[r * 8 + jt * 2 + (c >> 3)];
            v.x *= cr; v.y *= cr; v.z *= cr; v.w *= cr;
            *(float4*)(sAtt + r * CP + c * 4) = v;
        }
        for (int idx = t; idx < 32 * 16; idx += 256) {
            int r = idx >> 4, c = idx & 15;
            *(float4*)(sX + r * CP + c * 4) =
                *(const float4*)(x + ((size_t)b * WIN + w0 + r) * KF + j0 + c * 4);
        }
        __syncthreads();

        const ulonglong2* aq0 = (const ulonglong2*)(sAtt + il * CP);
        const ulonglong2* aq1 = (const ulonglong2*)(sAtt + (il + 16) * CP);
        const ulonglong2* xq0 = (const ulonglong2*)(sX + tw * CP);
        const ulonglong2* xq1 = (const ulonglong2*)(sX + (tw + 16) * CP);

        #pragma unroll 8
        for (int s = 0; s < 16; ++s) {
            ulonglong2 x0 = xq0[s], x1 = xq1[s];
            ulonglong2 a0 = aq0[s], a1 = aq1[s];
            FMA2(acc00, a0.x, x0.x, acc00);
            FMA2(acc00, a0.y, x0.y, acc00);
            FMA2(acc01, a0.x, x1.x, acc01);
            FMA2(acc01, a0.y, x1.y, acc01);
            FMA2(acc10, a1.x, x0.x, acc10);
            FMA2(acc10, a1.y, x0.y, acc10);
            FMA2(acc11, a1.x, x1.x, acc11);
            FMA2(acc11, a1.y, x1.y, acc11);
        }
    }

    __syncthreads();
    float lo, hi;
    UNPK(lo, hi, acc00); sOut[tw * 36 + il]             = 1.0f / (1.0f + __expf(-(lo + hi)));
    UNPK(lo, hi, acc01); sOut[(tw + 16) * 36 + il]      = 1.0f / (1.0f + __expf(-(lo + hi)));
    UNPK(lo, hi, acc10); sOut[tw * 36 + il + 16]        = 1.0f / (1.0f + __expf(-(lo + hi)));
    UNPK(lo, hi, acc11); sOut[(tw + 16) * 36 + il + 16] = 1.0f / (1.0f + __expf(-(lo + hi)));
    __syncthreads();
    for (int idx = t; idx < 32 * 32; idx += 256) {
        int r = idx >> 5, c = idx & 31;
        out[((size_t)b * WIN + w0 + r) * KF + i0 + c] = sOut[r * 36 + c];
    }
}

// ============================================================================
extern "C" void kernel_launch(void* const* d_in, const int* in_sizes, int n_in,
                              void* d_out, int out_size)
{
    const float* x   = (const float*)d_in[0];
    const float* lw  = (const float*)d_in[1];
    const float* lb  = (const float*)d_in[2];
    const float* a   = (const float*)d_in[3];
    const float* ab  = (const float*)d_in[4];
    float* out = (float*)d_out;

    cudaFuncSetAttribute(gemmA_mma, cudaFuncAttributeMaxDynamicSharedMemorySize, SM_GA_TOTAL);
    cudaFuncSetAttribute(kernB, cudaFuncAttributeMaxDynamicSharedMemorySize, SMB);

    gemmA_mma<<<dim3(4, 32), 512, SM_GA_TOTAL>>>(x, lw, lb);
    kernB<<<dim3(8, 8, NB), 256, SMB>>>(a, ab);
    kernC<<<dim3(8, 4, NB), 256>>>(x, out);
}